// round 10
// baseline (speedup 1.0000x reference)
#include <cuda_runtime.h>
#include <stdint.h>

#define N_NODES 200000
#define N_ETYPES 4
#define N_EDGES 500000
#define DIM 128
#define M_BINS (N_ETYPES * N_NODES)       // 800000 (etype, dst) bins
#define TOTAL_EDGES (N_ETYPES * N_EDGES)  // 2000000
#define SCAN_B 1024
#define NB ((M_BINS + SCAN_B - 1) / SCAN_B)   // 782 scan blocks

// ---------------- scratch (static __device__ — no allocations) ----------------
__device__ int g_cnt[M_BINS];        // per-(etype,dst) in-degree
__device__ int g_off[M_BINS];        // CSR row offsets (exclusive scan of cnt)
__device__ int g_cur[M_BINS];        // bucket cursors (copy of offsets)
__device__ int g_csr[TOTAL_EDGES];   // src node ids grouped by (etype,dst)
__device__ int g_bsum[SCAN_B];       // scan block sums (NB <= 1024)

// ---------------- prep kernels -------------------------------------------------
__global__ void zero_cnt_kernel() {
    int i = blockIdx.x * blockDim.x + threadIdx.x;
    if (i < M_BINS) g_cnt[i] = 0;
}

__global__ void count_kernel(const int* __restrict__ dst) {
    int i = blockIdx.x * blockDim.x + threadIdx.x;
    if (i < TOTAL_EDGES) {
        int t = i / N_EDGES;
        atomicAdd(&g_cnt[t * N_NODES + dst[i]], 1);
    }
}

// scan phase a: per-block sums of g_cnt
__global__ __launch_bounds__(SCAN_B)
void scan_sums_kernel() {
    __shared__ int s[SCAN_B];
    int t = threadIdx.x;
    int i = blockIdx.x * SCAN_B + t;
    s[t] = (i < M_BINS) ? g_cnt[i] : 0;
    __syncthreads();
#pragma unroll
    for (int o = SCAN_B / 2; o > 0; o >>= 1) {
        if (t < o) s[t] += s[t + o];
        __syncthreads();
    }
    if (t == 0) g_bsum[blockIdx.x] = s[0];
}

// scan phase b: single-block exclusive scan of block sums
__global__ __launch_bounds__(SCAN_B)
void scan_tops_kernel() {
    __shared__ int s[SCAN_B];
    int t = threadIdx.x;
    int own = (t < NB) ? g_bsum[t] : 0;
    s[t] = own;
    __syncthreads();
#pragma unroll
    for (int o = 1; o < SCAN_B; o <<= 1) {
        int v = (t >= o) ? s[t - o] : 0;
        __syncthreads();
        s[t] += v;
        __syncthreads();
    }
    if (t < NB) g_bsum[t] = s[t] - own;   // exclusive
}

// scan phase c: per-block exclusive scan + base -> offsets + cursor copy
__global__ __launch_bounds__(SCAN_B)
void scan_final_kernel() {
    __shared__ int s[SCAN_B];
    int t = threadIdx.x;
    int i = blockIdx.x * SCAN_B + t;
    int own = (i < M_BINS) ? g_cnt[i] : 0;
    s[t] = own;
    __syncthreads();
#pragma unroll
    for (int o = 1; o < SCAN_B; o <<= 1) {
        int v = (t >= o) ? s[t - o] : 0;
        __syncthreads();
        s[t] += v;
        __syncthreads();
    }
    if (i < M_BINS) {
        int ex = s[t] - own + g_bsum[blockIdx.x];
        g_off[i] = ex;
        g_cur[i] = ex;
    }
}

// bucket: scatter src ids into CSR order
__global__ void bucket_kernel(const int* __restrict__ src,
                              const int* __restrict__ dst) {
    int i = blockIdx.x * blockDim.x + threadIdx.x;
    if (i < TOTAL_EDGES) {
        int t = i / N_EDGES;
        int pos = atomicAdd(&g_cur[t * N_NODES + dst[i]], 1);
        g_csr[pos] = src[i];
    }
}

// ---------------- mega kernel: aggregate-then-transform ------------------------
// Per block: 128 dst rows. Phase 0: A = x rows (self term, W_self).
// Phase p=1..4: A = mean of x[src] over CSR edges of etype p-1 (built in smem,
// no atomics, gathers hit L2 since x fits), MMA with W_{p-1}, accumulate.
// Epilogue: + b_self + sum_t [cnt_t>0] * b_t, single streaming store to out.
// 512 threads = 16 warps: 4(m) x 4(n); warp tile 32x32 = 2 m16 x 4 n8.

#define BM 128
#define AS 132    // A smem stride: frag bank = (4g+tg)%32 -> conflict-free
#define BSD 136   // B smem stride: frag bank = (8tg+g)%32 -> conflict-free
#define SMEM_FLOATS (BM * AS + 2 * DIM * BSD)
#define SMEM_BYTES (SMEM_FLOATS * 4)

__device__ __forceinline__ uint32_t f2tf32(float f) {
    uint32_t u;
    asm("cvt.rna.tf32.f32 %0, %1;" : "=r"(u) : "f"(f));
    return u;
}

__device__ __forceinline__ void mma_tf32(float c[4], const uint32_t a[4],
                                         const uint32_t bb[2]) {
    asm volatile(
        "mma.sync.aligned.m16n8k8.row.col.f32.tf32.tf32.f32 "
        "{%0,%1,%2,%3}, {%4,%5,%6,%7}, {%8,%9}, {%0,%1,%2,%3};"
        : "+f"(c[0]), "+f"(c[1]), "+f"(c[2]), "+f"(c[3])
        : "r"(a[0]), "r"(a[1]), "r"(a[2]), "r"(a[3]), "r"(bb[0]), "r"(bb[1]));
}

__device__ __forceinline__ void cp_async_tile512(float* sdst,
                                                 const float* __restrict__ gsrc,
                                                 int tid) {
#pragma unroll
    for (int it = 0; it < 8; it++) {
        int idx = tid + it * 512;
        int r   = idx >> 5;            // 0..127
        int c4  = (idx & 31) * 4;      // 0..124
        uint32_t s = (uint32_t)__cvta_generic_to_shared(sdst + r * BSD + c4);
        asm volatile("cp.async.ca.shared.global [%0], [%1], 16;"
                     :: "r"(s), "l"(gsrc + (size_t)r * DIM + c4));
    }
}

__global__ __launch_bounds__(512, 1)
void mega_kernel(const float* __restrict__ x,
                 const float* __restrict__ W,
                 const float* __restrict__ b,
                 const float* __restrict__ W_self,
                 const float* __restrict__ b_self,
                 float* __restrict__ out) {
    extern __shared__ float smem[];
    float* As    = smem;               // [BM][AS], tf32 bit patterns
    float* BsAll = smem + BM * AS;     // [2][DIM][BSD], raw fp32 via cp.async
    __shared__ unsigned char mask8[N_ETYPES][BM];

    const int row0 = blockIdx.x * BM;
    const int tid  = threadIdx.x;
    const int warp = tid >> 5;         // 0..15
    const int lane = tid & 31;
    const int wm   = warp >> 2;        // 0..3  (32 rows each)
    const int wn   = warp & 3;         // 0..3  (32 cols each)
    const int g    = lane >> 2;        // 0..7
    const int tg   = lane & 3;         // 0..3

    const float* Bm[5] = {W_self, W, W + DIM * DIM, W + 2 * DIM * DIM,
                          W + 3 * DIM * DIM};

    // prefetch W_self -> buf0 (group 0)
    cp_async_tile512(BsAll, Bm[0], tid);
    asm volatile("cp.async.commit_group;");

    // stage x tile -> As (tf32): phase-0 A operand (also self rows)
#pragma unroll
    for (int it = 0; it < 8; it++) {
        int idx = tid + it * 512;
        int r   = idx >> 5;
        int c4  = (idx & 31) * 4;
        int gr  = row0 + r;
        float4 v = make_float4(0.f, 0.f, 0.f, 0.f);
        if (gr < N_NODES)
            v = *reinterpret_cast<const float4*>(x + (size_t)gr * DIM + c4);
        uint4 t;
        t.x = f2tf32(v.x); t.y = f2tf32(v.y);
        t.z = f2tf32(v.z); t.w = f2tf32(v.w);
        *reinterpret_cast<uint4*>(&As[r * AS + c4]) = t;
    }

    float acc[2][4][4];
#pragma unroll
    for (int i = 0; i < 2; i++)
#pragma unroll
        for (int j = 0; j < 4; j++)
#pragma unroll
            for (int k = 0; k < 4; k++) acc[i][j][k] = 0.0f;

    for (int p = 0; p < 5; p++) {
        if (p < 4) {
            cp_async_tile512(BsAll + ((p + 1) & 1) * (DIM * BSD), Bm[p + 1], tid);
            asm volatile("cp.async.commit_group;");
            asm volatile("cp.async.wait_group 1;" ::: "memory");
        } else {
            asm volatile("cp.async.wait_group 0;" ::: "memory");
        }
        __syncthreads();   // As content + current W visible to all

        float* Bbuf = BsAll + (p & 1) * (DIM * BSD);

        // ---- MMA: acc += A @ W[p] ----
#pragma unroll
        for (int ks = 0; ks < DIM; ks += 8) {
            uint32_t afr[2][4];
#pragma unroll
            for (int mt = 0; mt < 2; mt++) {
                int r = wm * 32 + mt * 16 + g;
                afr[mt][0] = __float_as_uint(As[r * AS + ks + tg]);
                afr[mt][1] = __float_as_uint(As[(r + 8) * AS + ks + tg]);
                afr[mt][2] = __float_as_uint(As[r * AS + ks + tg + 4]);
                afr[mt][3] = __float_as_uint(As[(r + 8) * AS + ks + tg + 4]);
            }
            uint32_t bfr[4][2];
#pragma unroll
            for (int nt = 0; nt < 4; nt++) {
                int c = wn * 32 + nt * 8 + g;
                bfr[nt][0] = f2tf32(Bbuf[(ks + tg) * BSD + c]);
                bfr[nt][1] = f2tf32(Bbuf[(ks + tg + 4) * BSD + c]);
            }
#pragma unroll
            for (int mt = 0; mt < 2; mt++)
#pragma unroll
                for (int nt = 0; nt < 4; nt++)
                    mma_tf32(acc[mt][nt], afr[mt], bfr[nt]);
        }

        // ---- build next A: per-(etype p, dst) mean of x[src] (CSR, no atomics)
        if (p < 4) {
            __syncthreads();   // all warps done reading As
            const int t = p;
            const int rbase = warp * 8;   // 16 warps x 8 rows = 128
#pragma unroll 1
            for (int rr = 0; rr < 8; rr++) {
                int r = rbase + rr;
                int d = row0 + r;
                int n = 0, base = 0;
                if (d < N_NODES) {
                    int bin = t * N_NODES + d;
                    n    = g_cnt[bin];
                    base = g_off[bin];
                }
                float4 a0 = make_float4(0.f, 0.f, 0.f, 0.f);
                float4 a1 = make_float4(0.f, 0.f, 0.f, 0.f);
                int j = 0;
                for (; j + 2 <= n; j += 2) {
                    int s0 = g_csr[base + j];
                    int s1 = g_csr[base + j + 1];
                    float4 v0 = *reinterpret_cast<const float4*>(
                        x + (size_t)s0 * DIM + (lane << 2));
                    float4 v1 = *reinterpret_cast<const float4*>(
                        x + (size_t)s1 * DIM + (lane << 2));
                    a0.x += v0.x; a0.y += v0.y; a0.z += v0.z; a0.w += v0.w;
                    a1.x += v1.x; a1.y += v1.y; a1.z += v1.z; a1.w += v1.w;
                }
                if (j < n) {
                    int s0 = g_csr[base + j];
                    float4 v0 = *reinterpret_cast<const float4*>(
                        x + (size_t)s0 * DIM + (lane << 2));
                    a0.x += v0.x; a0.y += v0.y; a0.z += v0.z; a0.w += v0.w;
                }
                float sc = (n > 0) ? (1.0f / (float)n) : 0.0f;
                uint4 tt;
                tt.x = f2tf32((a0.x + a1.x) * sc);
                tt.y = f2tf32((a0.y + a1.y) * sc);
                tt.z = f2tf32((a0.z + a1.z) * sc);
                tt.w = f2tf32((a0.w + a1.w) * sc);
                *reinterpret_cast<uint4*>(&As[r * AS + (lane << 2)]) = tt;
                if (lane == 0) mask8[t][r] = (n > 0) ? 1 : 0;
            }
            // next iteration's __syncthreads publishes As + mask8
        }
    }

    // ---- epilogue: masked biases + store ----
#pragma unroll
    for (int nt = 0; nt < 4; nt++) {
        int c = wn * 32 + nt * 8 + tg * 2;
        float bs0 = __ldg(&b_self[c]);
        float bs1 = __ldg(&b_self[c + 1]);
        float bt0[N_ETYPES], bt1[N_ETYPES];
#pragma unroll
        for (int t = 0; t < N_ETYPES; t++) {
            bt0[t] = __ldg(&b[t * DIM + c]);
            bt1[t] = __ldg(&b[t * DIM + c + 1]);
        }
#pragma unroll
        for (int mt = 0; mt < 2; mt++) {
            int r_lo = wm * 32 + mt * 16 + g;
#pragma unroll
            for (int half = 0; half < 2; half++) {
                int r = r_lo + half * 8;
                if (row0 + r >= N_NODES) continue;
                float v0 = acc[mt][nt][half * 2 + 0] + bs0;
                float v1 = acc[mt][nt][half * 2 + 1] + bs1;
#pragma unroll
                for (int t = 0; t < N_ETYPES; t++) {
                    if (mask8[t][r]) { v0 += bt0[t]; v1 += bt1[t]; }
                }
                *reinterpret_cast<float2*>(out + (size_t)(row0 + r) * DIM + c) =
                    make_float2(v0, v1);
            }
        }
    }
}

// ---------------- launcher ----------------
extern "C" void kernel_launch(void* const* d_in, const int* in_sizes, int n_in,
                              void* d_out, int out_size) {
    const float* x      = (const float*)d_in[0];   // [200000,128]
    const float* W      = (const float*)d_in[1];   // [4,128,128]
    const float* b      = (const float*)d_in[2];   // [4,128]
    const float* W_self = (const float*)d_in[3];   // [128,128]
    const float* b_self = (const float*)d_in[4];   // [128]
    const int*   src    = (const int*)d_in[5];     // [4,500000]
    const int*   dst    = (const int*)d_in[6];     // [4,500000]
    float* out = (float*)d_out;                    // [200000,128]

    (void)in_sizes; (void)n_in; (void)out_size;

    // --- CSR build: count -> scan -> bucket ---
    zero_cnt_kernel<<<(M_BINS + 255) / 256, 256>>>();
    count_kernel<<<(TOTAL_EDGES + 255) / 256, 256>>>(dst);
    scan_sums_kernel<<<NB, SCAN_B>>>();
    scan_tops_kernel<<<1, SCAN_B>>>();
    scan_final_kernel<<<NB, SCAN_B>>>();
    bucket_kernel<<<(TOTAL_EDGES + 255) / 256, 256>>>(src, dst);

    // --- fused aggregate + 5-way tf32 GEMM ---
    cudaFuncSetAttribute(mega_kernel,
                         cudaFuncAttributeMaxDynamicSharedMemorySize,
                         SMEM_BYTES);
    int grid = (N_NODES + BM - 1) / BM;
    mega_kernel<<<grid, 512, SMEM_BYTES>>>(x, W, b, W_self, b_self, out);
}

// round 11
// speedup vs baseline: 1.0108x; 1.0108x over previous
#include <cuda_runtime.h>
#include <stdint.h>

#define N_NODES 200000
#define N_ETYPES 4
#define N_EDGES 500000
#define DIM 128
#define M_BINS (N_ETYPES * N_NODES)       // 800000 (etype, dst) bins
#define TOTAL_EDGES (N_ETYPES * N_EDGES)  // 2000000
#define SCAN_B 1024
#define NB ((M_BINS + SCAN_B - 1) / SCAN_B)   // 782 scan blocks

// ---------------- scratch (static __device__ — no allocations) ----------------
__device__ int g_cnt[M_BINS];        // per-(etype,dst) in-degree
__device__ int g_off[M_BINS];        // CSR row offsets (exclusive scan of cnt)
__device__ int g_cur[M_BINS];        // bucket cursors (copy of offsets)
__device__ int g_csr[TOTAL_EDGES];   // src node ids grouped by (etype,dst)
__device__ int g_bsum[SCAN_B];       // scan block sums (NB <= 1024)

// ---------------- prep kernels -------------------------------------------------
__global__ void zero_cnt_kernel() {
    int i = blockIdx.x * blockDim.x + threadIdx.x;
    if (i < M_BINS) g_cnt[i] = 0;
}

__global__ void count_kernel(const int* __restrict__ dst) {
    int i = blockIdx.x * blockDim.x + threadIdx.x;
    if (i < TOTAL_EDGES) {
        int t = i / N_EDGES;
        atomicAdd(&g_cnt[t * N_NODES + dst[i]], 1);
    }
}

// scan phase a: per-block sums of g_cnt
__global__ __launch_bounds__(SCAN_B)
void scan_sums_kernel() {
    __shared__ int s[SCAN_B];
    int t = threadIdx.x;
    int i = blockIdx.x * SCAN_B + t;
    s[t] = (i < M_BINS) ? g_cnt[i] : 0;
    __syncthreads();
#pragma unroll
    for (int o = SCAN_B / 2; o > 0; o >>= 1) {
        if (t < o) s[t] += s[t + o];
        __syncthreads();
    }
    if (t == 0) g_bsum[blockIdx.x] = s[0];
}

// scan phase b: single-block exclusive scan of block sums
__global__ __launch_bounds__(SCAN_B)
void scan_tops_kernel() {
    __shared__ int s[SCAN_B];
    int t = threadIdx.x;
    int own = (t < NB) ? g_bsum[t] : 0;
    s[t] = own;
    __syncthreads();
#pragma unroll
    for (int o = 1; o < SCAN_B; o <<= 1) {
        int v = (t >= o) ? s[t - o] : 0;
        __syncthreads();
        s[t] += v;
        __syncthreads();
    }
    if (t < NB) g_bsum[t] = s[t] - own;   // exclusive
}

// scan phase c: per-block exclusive scan + base -> offsets + cursor copy
__global__ __launch_bounds__(SCAN_B)
void scan_final_kernel() {
    __shared__ int s[SCAN_B];
    int t = threadIdx.x;
    int i = blockIdx.x * SCAN_B + t;
    int own = (i < M_BINS) ? g_cnt[i] : 0;
    s[t] = own;
    __syncthreads();
#pragma unroll
    for (int o = 1; o < SCAN_B; o <<= 1) {
        int v = (t >= o) ? s[t - o] : 0;
        __syncthreads();
        s[t] += v;
        __syncthreads();
    }
    if (i < M_BINS) {
        int ex = s[t] - own + g_bsum[blockIdx.x];
        g_off[i] = ex;
        g_cur[i] = ex;
    }
}

// bucket: scatter src ids into CSR order
__global__ void bucket_kernel(const int* __restrict__ src,
                              const int* __restrict__ dst) {
    int i = blockIdx.x * blockDim.x + threadIdx.x;
    if (i < TOTAL_EDGES) {
        int t = i / N_EDGES;
        int pos = atomicAdd(&g_cur[t * N_NODES + dst[i]], 1);
        g_csr[pos] = src[i];
    }
}

// ---------------- mega kernel: aggregate-then-transform ------------------------
// Per block: 128 dst rows. Phase 0: A = x rows (self term, W_self).
// Phase p=1..4: A = mean of x[src] over CSR edges of etype p-1 (built in smem,
// no atomics, gathers hit L2 since x fits), MMA with W_{p-1}, accumulate.
// Epilogue: + b_self + sum_t [cnt_t>0] * b_t, single streaming store to out.
// 512 threads = 16 warps: 4(m) x 4(n); warp tile 32x32 = 2 m16 x 4 n8.

#define BM 128
#define AS 132    // A smem stride: frag bank = (4g+tg)%32 -> conflict-free
#define BSD 136   // B smem stride: frag bank = (8tg+g)%32 -> conflict-free
#define SMEM_FLOATS (BM * AS + 2 * DIM * BSD)
#define SMEM_BYTES (SMEM_FLOATS * 4)

__device__ __forceinline__ uint32_t f2tf32(float f) {
    uint32_t u;
    asm("cvt.rna.tf32.f32 %0, %1;" : "=r"(u) : "f"(f));
    return u;
}

__device__ __forceinline__ void mma_tf32(float c[4], const uint32_t a[4],
                                         const uint32_t bb[2]) {
    asm volatile(
        "mma.sync.aligned.m16n8k8.row.col.f32.tf32.tf32.f32 "
        "{%0,%1,%2,%3}, {%4,%5,%6,%7}, {%8,%9}, {%0,%1,%2,%3};"
        : "+f"(c[0]), "+f"(c[1]), "+f"(c[2]), "+f"(c[3])
        : "r"(a[0]), "r"(a[1]), "r"(a[2]), "r"(a[3]), "r"(bb[0]), "r"(bb[1]));
}

__device__ __forceinline__ void cp_async_tile512(float* sdst,
                                                 const float* __restrict__ gsrc,
                                                 int tid) {
#pragma unroll
    for (int it = 0; it < 8; it++) {
        int idx = tid + it * 512;
        int r   = idx >> 5;            // 0..127
        int c4  = (idx & 31) * 4;      // 0..124
        uint32_t s = (uint32_t)__cvta_generic_to_shared(sdst + r * BSD + c4);
        asm volatile("cp.async.ca.shared.global [%0], [%1], 16;"
                     :: "r"(s), "l"(gsrc + (size_t)r * DIM + c4));
    }
}

__global__ __launch_bounds__(512, 1)
void mega_kernel(const float* __restrict__ x,
                 const float* __restrict__ W,
                 const float* __restrict__ b,
                 const float* __restrict__ W_self,
                 const float* __restrict__ b_self,
                 float* __restrict__ out) {
    extern __shared__ float smem[];
    float* As    = smem;               // [BM][AS], tf32 bit patterns
    float* BsAll = smem + BM * AS;     // [2][DIM][BSD], raw fp32 via cp.async
    __shared__ unsigned char mask8[N_ETYPES][BM];

    const int row0 = blockIdx.x * BM;
    const int tid  = threadIdx.x;
    const int warp = tid >> 5;         // 0..15
    const int lane = tid & 31;
    const int wm   = warp >> 2;        // 0..3  (32 rows each)
    const int wn   = warp & 3;         // 0..3  (32 cols each)
    const int g    = lane >> 2;        // 0..7
    const int tg   = lane & 3;         // 0..3

    const float* Bm[5] = {W_self, W, W + DIM * DIM, W + 2 * DIM * DIM,
                          W + 3 * DIM * DIM};

    // prefetch W_self -> buf0 (group 0)
    cp_async_tile512(BsAll, Bm[0], tid);
    asm volatile("cp.async.commit_group;");

    // stage x tile -> As (tf32): phase-0 A operand (also self rows)
#pragma unroll
    for (int it = 0; it < 8; it++) {
        int idx = tid + it * 512;
        int r   = idx >> 5;
        int c4  = (idx & 31) * 4;
        int gr  = row0 + r;
        float4 v = make_float4(0.f, 0.f, 0.f, 0.f);
        if (gr < N_NODES)
            v = *reinterpret_cast<const float4*>(x + (size_t)gr * DIM + c4);
        uint4 t;
        t.x = f2tf32(v.x); t.y = f2tf32(v.y);
        t.z = f2tf32(v.z); t.w = f2tf32(v.w);
        *reinterpret_cast<uint4*>(&As[r * AS + c4]) = t;
    }

    float acc[2][4][4];
#pragma unroll
    for (int i = 0; i < 2; i++)
#pragma unroll
        for (int j = 0; j < 4; j++)
#pragma unroll
            for (int k = 0; k < 4; k++) acc[i][j][k] = 0.0f;

    for (int p = 0; p < 5; p++) {
        if (p < 4) {
            cp_async_tile512(BsAll + ((p + 1) & 1) * (DIM * BSD), Bm[p + 1], tid);
            asm volatile("cp.async.commit_group;");
            asm volatile("cp.async.wait_group 1;" ::: "memory");
        } else {
            asm volatile("cp.async.wait_group 0;" ::: "memory");
        }
        __syncthreads();   // As content + current W visible to all

        float* Bbuf = BsAll + (p & 1) * (DIM * BSD);

        // ---- MMA: acc += A @ W[p] ----
#pragma unroll
        for (int ks = 0; ks < DIM; ks += 8) {
            uint32_t afr[2][4];
#pragma unroll
            for (int mt = 0; mt < 2; mt++) {
                int r = wm * 32 + mt * 16 + g;
                afr[mt][0] = __float_as_uint(As[r * AS + ks + tg]);
                afr[mt][1] = __float_as_uint(As[(r + 8) * AS + ks + tg]);
                afr[mt][2] = __float_as_uint(As[r * AS + ks + tg + 4]);
                afr[mt][3] = __float_as_uint(As[(r + 8) * AS + ks + tg + 4]);
            }
            uint32_t bfr[4][2];
#pragma unroll
            for (int nt = 0; nt < 4; nt++) {
                int c = wn * 32 + nt * 8 + g;
                bfr[nt][0] = f2tf32(Bbuf[(ks + tg) * BSD + c]);
                bfr[nt][1] = f2tf32(Bbuf[(ks + tg + 4) * BSD + c]);
            }
#pragma unroll
            for (int mt = 0; mt < 2; mt++)
#pragma unroll
                for (int nt = 0; nt < 4; nt++)
                    mma_tf32(acc[mt][nt], afr[mt], bfr[nt]);
        }

        // ---- build next A: per-(etype p, dst) mean of x[src] (CSR, no atomics)
        if (p < 4) {
            __syncthreads();   // all warps done reading As
            const int t = p;
            const int rbase = warp * 8;   // 16 warps x 8 rows = 128
#pragma unroll 1
            for (int rr = 0; rr < 8; rr++) {
                int r = rbase + rr;
                int d = row0 + r;
                int n = 0, base = 0;
                if (d < N_NODES) {
                    int bin = t * N_NODES + d;
                    n    = g_cnt[bin];
                    base = g_off[bin];
                }
                float4 a0 = make_float4(0.f, 0.f, 0.f, 0.f);
                float4 a1 = make_float4(0.f, 0.f, 0.f, 0.f);
                int j = 0;
                for (; j + 2 <= n; j += 2) {
                    int s0 = g_csr[base + j];
                    int s1 = g_csr[base + j + 1];
                    float4 v0 = *reinterpret_cast<const float4*>(
                        x + (size_t)s0 * DIM + (lane << 2));
                    float4 v1 = *reinterpret_cast<const float4*>(
                        x + (size_t)s1 * DIM + (lane << 2));
                    a0.x += v0.x; a0.y += v0.y; a0.z += v0.z; a0.w += v0.w;
                    a1.x += v1.x; a1.y += v1.y; a1.z += v1.z; a1.w += v1.w;
                }
                if (j < n) {
                    int s0 = g_csr[base + j];
                    float4 v0 = *reinterpret_cast<const float4*>(
                        x + (size_t)s0 * DIM + (lane << 2));
                    a0.x += v0.x; a0.y += v0.y; a0.z += v0.z; a0.w += v0.w;
                }
                float sc = (n > 0) ? (1.0f / (float)n) : 0.0f;
                uint4 tt;
                tt.x = f2tf32((a0.x + a1.x) * sc);
                tt.y = f2tf32((a0.y + a1.y) * sc);
                tt.z = f2tf32((a0.z + a1.z) * sc);
                tt.w = f2tf32((a0.w + a1.w) * sc);
                *reinterpret_cast<uint4*>(&As[r * AS + (lane << 2)]) = tt;
                if (lane == 0) mask8[t][r] = (n > 0) ? 1 : 0;
            }
            // next iteration's __syncthreads publishes As + mask8
        }
    }

    // ---- epilogue: masked biases + store ----
#pragma unroll
    for (int nt = 0; nt < 4; nt++) {
        int c = wn * 32 + nt * 8 + tg * 2;
        float bs0 = __ldg(&b_self[c]);
        float bs1 = __ldg(&b_self[c + 1]);
        float bt0[N_ETYPES], bt1[N_ETYPES];
#pragma unroll
        for (int t = 0; t < N_ETYPES; t++) {
            bt0[t] = __ldg(&b[t * DIM + c]);
            bt1[t] = __ldg(&b[t * DIM + c + 1]);
        }
#pragma unroll
        for (int mt = 0; mt < 2; mt++) {
            int r_lo = wm * 32 + mt * 16 + g;
#pragma unroll
            for (int half = 0; half < 2; half++) {
                int r = r_lo + half * 8;
                if (row0 + r >= N_NODES) continue;
                float v0 = acc[mt][nt][half * 2 + 0] + bs0;
                float v1 = acc[mt][nt][half * 2 + 1] + bs1;
#pragma unroll
                for (int t = 0; t < N_ETYPES; t++) {
                    if (mask8[t][r]) { v0 += bt0[t]; v1 += bt1[t]; }
                }
                *reinterpret_cast<float2*>(out + (size_t)(row0 + r) * DIM + c) =
                    make_float2(v0, v1);
            }
        }
    }
}

// ---------------- launcher ----------------
extern "C" void kernel_launch(void* const* d_in, const int* in_sizes, int n_in,
                              void* d_out, int out_size) {
    const float* x      = (const float*)d_in[0];   // [200000,128]
    const float* W      = (const float*)d_in[1];   // [4,128,128]
    const float* b      = (const float*)d_in[2];   // [4,128]
    const float* W_self = (const float*)d_in[3];   // [128,128]
    const float* b_self = (const float*)d_in[4];   // [128]
    const int*   src    = (const int*)d_in[5];     // [4,500000]
    const int*   dst    = (const int*)d_in[6];     // [4,500000]
    float* out = (float*)d_out;                    // [200000,128]

    (void)in_sizes; (void)n_in; (void)out_size;

    // --- CSR build: count -> scan -> bucket ---
    zero_cnt_kernel<<<(M_BINS + 255) / 256, 256>>>();
    count_kernel<<<(TOTAL_EDGES + 255) / 256, 256>>>(dst);
    scan_sums_kernel<<<NB, SCAN_B>>>();
    scan_tops_kernel<<<1, SCAN_B>>>();
    scan_final_kernel<<<NB, SCAN_B>>>();
    bucket_kernel<<<(TOTAL_EDGES + 255) / 256, 256>>>(src, dst);

    // --- fused aggregate + 5-way tf32 GEMM ---
    cudaFuncSetAttribute(mega_kernel,
                         cudaFuncAttributeMaxDynamicSharedMemorySize,
                         SMEM_BYTES);
    int grid = (N_NODES + BM - 1) / BM;
    mega_kernel<<<grid, 512, SMEM_BYTES>>>(x, W, b, W_self, b_self, out);
}